// round 10
// baseline (speedup 1.0000x reference)
#include <cuda_runtime.h>
#include <cuda_bf16.h>
#include <cstdint>

#define A_DIM 512
#define C_DIM 345
#define N_DIM 128
#define CPAD  384

#define SW_SCALE 64.0f     // W  -> e4m3 scale
#define SS_SCALE 256.0f    // Sig-> e4m3 scale
#define INV_PSCALE (1.0f / (64.0f * 256.0f))

// ---------------------------------------------------------------------------
// Scratch (device globals; no allocation allowed)
// ---------------------------------------------------------------------------
__device__ __align__(1024) uint32_t g_S8[(size_t)N_DIM * A_DIM * A_DIM / 4]; // e4m3 Sig x256, [slot][a][b] 34MB
__device__ __align__(1024) uint32_t g_W8[CPAD * A_DIM / 4];                  // e4m3 W x64
__device__ float g_f4[4][N_DIM][CPAD];    // partial f per a-chunk
__device__ float g_nll[N_DIM];
__device__ int   g_slot[N_DIM];
__device__ int   g_first[N_DIM];

// ---------------------------------------------------------------------------
// Helpers
// ---------------------------------------------------------------------------
__device__ __forceinline__ uint32_t smem_u32(const void* p) {
    uint32_t a;
    asm("{ .reg .u64 t; cvta.to.shared.u64 t, %1; cvt.u32.u64 %0, t; }" : "=r"(a) : "l"(p));
    return a;
}
__device__ __forceinline__ void cp16(uint32_t dst, const void* src) {
    asm volatile("cp.async.cg.shared.global [%0], [%1], 16;" :: "r"(dst), "l"(src));
}
#define CP_COMMIT() asm volatile("cp.async.commit_group;")
#define CP_WAIT(N)  asm volatile("cp.async.wait_group %0;" :: "n"(N))

#define LDSM4(r0, r1, r2, r3, addr)                                            \
    asm volatile("ldmatrix.sync.aligned.m8n8.x4.shared.b16 {%0,%1,%2,%3}, [%4];" \
        : "=r"(r0), "=r"(r1), "=r"(r2), "=r"(r3) : "r"(addr))

#define MMAFP8(d, a, b0, b1)                                                   \
    asm volatile("mma.sync.aligned.m16n8k32.row.col.f32.e4m3.e4m3.f32 "        \
        "{%0,%1,%2,%3},{%4,%5,%6,%7},{%8,%9},{%0,%1,%2,%3};"                   \
        : "+f"((d)[0]), "+f"((d)[1]), "+f"((d)[2]), "+f"((d)[3])               \
        : "r"((a)[0]), "r"((a)[1]), "r"((a)[2]), "r"((a)[3]), "r"(b0), "r"(b1))

// pack 4 floats -> 4 e4m3 bytes (little-endian x,y,z,w)
__device__ __forceinline__ uint32_t pack_e4m3x4(float x, float y, float z, float w) {
    unsigned short lo, hi;
    asm("cvt.rn.satfinite.e4m3x2.f32 %0, %1, %2;" : "=h"(lo) : "f"(y), "f"(x));
    asm("cvt.rn.satfinite.e4m3x2.f32 %0, %1, %2;" : "=h"(hi) : "f"(w), "f"(z));
    return (uint32_t)lo | ((uint32_t)hi << 16);
}
// 2 e4m3 bytes -> float2
__device__ __forceinline__ float2 fp8x2_f2(unsigned short v) {
    uint32_t h;
    asm("cvt.rn.f16x2.e4m3x2 %0, %1;" : "=r"(h) : "h"(v));
    const __half2 hh = *(const __half2*)&h;
    return __half22float2(hh);
}

// Label dtype detection (jax may emit int32 or int64)
__device__ __forceinline__ int label_is64(const void* lp) {
    const long long* p = (const long long*)lp;
    int ok = 1;
#pragma unroll 1
    for (int i = 0; i < 64; i++) {
        long long v = p[i];
        if (v < 0 || v >= C_DIM) { ok = 0; break; }
    }
    return ok;
}
__device__ __forceinline__ int get_label(const void* lp, int n, int is64) {
    return is64 ? (int)((const long long*)lp)[n] : ((const int*)lp)[n];
}

// ---------------------------------------------------------------------------
// prep: slot/first tables
// ---------------------------------------------------------------------------
__global__ void prep_labels(const void* __restrict__ labels) {
    const int t = threadIdx.x;
    const int is64 = label_is64(labels);
    const int ln = get_label(labels, t, is64);
    int slot = t, first = 1;
    for (int m = 0; m < t; m++)
        if (get_label(labels, m, is64) == ln) { slot = m; first = 0; break; }
    g_slot[t] = slot;
    g_first[t] = first;
}

// cast W*64 -> e4m3 (pad rows >= C_DIM with zeros). 128 threads/row.
__global__ void conv_w8(const float* __restrict__ Wg) {
    const int c = blockIdx.x, t = threadIdx.x;
    uint32_t packed;
    if (c < C_DIM) {
        const float4 w = *(const float4*)(Wg + (size_t)c * A_DIM + 4 * t);
        packed = pack_e4m3x4(w.x * SW_SCALE, w.y * SW_SCALE,
                             w.z * SW_SCALE, w.w * SW_SCALE);
    } else {
        packed = 0u;
    }
    g_W8[c * (A_DIM / 4) + t] = packed;
}

// cast Sigma_l*256 -> e4m3, row-major, for first-occurrence slots.
// Pure streaming cast: fully coalesced both sides.
__global__ __launch_bounds__(256, 8)
void conv_sig(const float* __restrict__ cov) {
    const int n = blockIdx.z;
    if (!g_first[n]) return;
    const int idx = blockIdx.x * 256 + threadIdx.x;   // float4 index, 65536 total
    const int l = g_slot[n];                          // slot == n for first; label row via labels below
    (void)l;
    // NOTE: need actual label l, stored via labels in gemm; here use label lookup:
    // we pass cov already offset per-slot from host? No host label access. Use g_lbl.
    // (g_lbl filled by prep2 below)
    extern __device__ int g_lbl[];
    const float4 v = *(const float4*)(cov + (size_t)g_lbl[n] * A_DIM * A_DIM + (size_t)idx * 4);
    g_S8[(size_t)n * (A_DIM * A_DIM / 4) + idx] =
        pack_e4m3x4(v.x * SS_SCALE, v.y * SS_SCALE, v.z * SS_SCALE, v.w * SS_SCALE);
}

__device__ int g_lbl[N_DIM];
__global__ void prep_lbl(const void* __restrict__ labels) {
    const int t = threadIdx.x;
    g_lbl[t] = get_label(labels, t, label_is64(labels));
}

// ---------------------------------------------------------------------------
// Main fp8 HMMA GEMM, a-split: CTA = (c-tile, a-chunk, slot).
//   Q[c,a] = sum_b W8[c,b] * S8[a,b]          (m=c, n=a, k=b; S8 row-major!)
//   u[a]   = sum_b Wl[b] * decode(S8[a,b])    (fp32 side-accumulation)
//   quad[c]+= sum_a (Q - 64*u)[c,a] * dw[c,a] / 16384
//   lin[c] += sum_a dw[c,a] * dM[a]
// ---------------------------------------------------------------------------
#define STG_A   0                       // 3 x 8192 (128 rows x 64B fp8)
#define STG_B   24576                   // 3 x 8192
#define OFF_WL  49152                   // 512 f32
#define OFF_DM  (OFF_WL + 2048)
#define OFF_Q   (OFF_DM + 2048)         // 128*2 f32
#define OFF_L   (OFF_Q + 1024)
#define OFF_VP  (OFF_L + 1024)          // 256 f32 u partials
#define SMEM_DYN (OFF_VP + 1024)

__global__ __launch_bounds__(256, 2)
void gemm_kernel(const float* __restrict__ Wg,
                 const float* __restrict__ Lam_p,
                 const float* __restrict__ ms,
                 const float* __restrict__ mt) {
    extern __shared__ __align__(128) char dsm[];
    const int n = blockIdx.z;
    if (!g_first[n]) return;
    const int ai = blockIdx.y;

    const uint32_t sb = smem_u32(dsm);
    float* sWl = (float*)(dsm + OFF_WL);
    float* sDM = (float*)(dsm + OFF_DM);
    float* sQ  = (float*)(dsm + OFF_Q);
    float* sL  = (float*)(dsm + OFF_L);
    float* sVP = (float*)(dsm + OFF_VP);

    const int c0 = blockIdx.x * 128;
    const int t = threadIdx.x;
    const int lane = t & 31, w = t >> 5;
    const int wm = w & 3, wn = w >> 2;

    const int l = g_lbl[n];
    for (int a = t; a < A_DIM; a += 256) {
        sWl[a] = Wg[(size_t)l * A_DIM + a];
        sDM[a] = mt[(size_t)l * A_DIM + a] - ms[(size_t)l * A_DIM + a];
    }
    __syncthreads();

    // per-lane ldmatrix geometry (byte layout identical to bf16-k16 case)
    const int lj = lane >> 3, li = lane & 7;
    const int amr0 = wm * 32 + (lj & 1) * 8 + li;
    const int amr1 = amr0 + 16;
    const int akc  = lj >> 1;
    const int asw0 = (amr0 >> 1) & 3, asw1 = (amr1 >> 1) & 3;
    int bnr[4], bsw[4];
#pragma unroll
    for (int np = 0; np < 4; np++) {
        bnr[np] = wn * 64 + np * 16 + (lj >> 1) * 8 + li;
        bsw[np] = (bnr[np] >> 1) & 3;
    }
    const int bkc = lj & 1;

    // u accumulation geometry: thread -> (a-row, 2 chunks of 16 fp8)
    const int vrow = t >> 1;
    const int vc0  = (t & 1) * 2;
    const uint32_t vof0 = (uint32_t)(vrow * 64 + (((vc0 + 0) ^ ((vrow >> 1) & 3)) << 4));
    const uint32_t vof1 = (uint32_t)(vrow * 64 + (((vc0 + 1) ^ ((vrow >> 1) & 3)) << 4));

    float D[2][8][4];
#pragma unroll
    for (int mi = 0; mi < 2; mi++)
#pragma unroll
        for (int ni = 0; ni < 8; ni++)
#pragma unroll
            for (int e = 0; e < 4; e++) D[mi][ni][e] = 0.f;
    float vacc = 0.f;

    const char* gW8b = (const char*)g_W8;
    const char* gS8b = (const char*)g_S8;

    auto stage = [&](int st, int ck) {
        const int b0 = ck * 64;   // byte == elem offset along k(b)
#pragma unroll
        for (int p = 0; p < 2; p++) {
            const int id = t + 256 * p;
            const int m = id >> 2, ch = id & 3;
            const uint32_t so = (uint32_t)(m * 64 + ((ch ^ ((m >> 1) & 3)) << 4));
            cp16(sb + STG_A + st * 8192 + so,
                 gW8b + (size_t)(c0 + m) * A_DIM + b0 + ch * 16);
            cp16(sb + STG_B + st * 8192 + so,
                 gS8b + ((size_t)n * A_DIM + ai * 128 + m) * A_DIM + b0 + ch * 16);
        }
        CP_COMMIT();
    };

    stage(0, 0); stage(1, 1); stage(2, 2);

    int st = 0;
#pragma unroll 1
    for (int k = 0; k < 8; k++) {
        if (k < 6) CP_WAIT(2);
        else if (k == 6) CP_WAIT(1);
        else CP_WAIT(0);
        __syncthreads();

        const uint32_t Ab = sb + STG_A + st * 8192;
        const uint32_t Bb = sb + STG_B + st * 8192;
#pragma unroll
        for (int s = 0; s < 2; s++) {
            uint32_t a0r[4], a1r[4], br[4][4];
            LDSM4(a0r[0], a0r[1], a0r[2], a0r[3],
                  Ab + amr0 * 64 + (((2 * s + akc) ^ asw0) << 4));
            LDSM4(a1r[0], a1r[1], a1r[2], a1r[3],
                  Ab + amr1 * 64 + (((2 * s + akc) ^ asw1) << 4));
#pragma unroll
            for (int np = 0; np < 4; np++)
                LDSM4(br[np][0], br[np][1], br[np][2], br[np][3],
                      Bb + bnr[np] * 64 + (((2 * s + bkc) ^ bsw[np]) << 4));
#pragma unroll
            for (int ni = 0; ni < 8; ni++) {
                const uint32_t b0 = br[ni >> 1][(ni & 1) * 2];
                const uint32_t b1 = br[ni >> 1][(ni & 1) * 2 + 1];
                MMAFP8(D[0][ni], a0r, b0, b1);
                MMAFP8(D[1][ni], a1r, b0, b1);
            }
        }
        // u side-accumulation from the staged B tile (fp8 decode, fp32 acc)
        {
            const char* Bp = dsm + STG_B + st * 8192;
            const uint4 p0 = *(const uint4*)(Bp + vof0);
            const uint4 p1 = *(const uint4*)(Bp + vof1);
            const unsigned short* h0 = (const unsigned short*)&p0;
            const unsigned short* h1 = (const unsigned short*)&p1;
            const float* wl0 = sWl + k * 64 + vc0 * 16;
#pragma unroll
            for (int j = 0; j < 8; j++) {
                const float2 f0 = fp8x2_f2(h0[j]);
                const float2 f1 = fp8x2_f2(h1[j]);
                vacc += f0.x * wl0[2 * j] + f0.y * wl0[2 * j + 1];
                vacc += f1.x * wl0[16 + 2 * j] + f1.y * wl0[16 + 2 * j + 1];
            }
        }
        __syncthreads();
        if (k + 3 < 8) stage(st, k + 3);
        st = (st == 2) ? 0 : st + 1;
    }

    sVP[t] = vacc;
    __syncthreads();

    // epilogue: contract Q-frags against dw, u, dM  (fp32 throughout)
    float qacc[4] = {0, 0, 0, 0}, lacc[4] = {0, 0, 0, 0};
#pragma unroll
    for (int mi = 0; mi < 2; mi++) {
        const int crb = c0 + wm * 32 + mi * 16 + (lane >> 2);
#pragma unroll
        for (int half = 0; half < 2; half++) {
            const int cr = crb + half * 8;
            if (cr < C_DIM) {
                const float* wrow = Wg + (size_t)cr * A_DIM;
                float q = 0.f, li2 = 0.f;
#pragma unroll
                for (int ni = 0; ni < 8; ni++) {
                    const int al = wn * 64 + ni * 8 + (lane & 3) * 2;  // local a
                    const int a  = ai * 128 + al;                      // global a
                    const float2 wv = *(const float2*)(wrow + a);
                    const float dw0 = wv.x - sWl[a], dw1 = wv.y - sWl[a + 1];
                    const float u0 = SW_SCALE * (sVP[2 * al] + sVP[2 * al + 1]);
                    const float u1 = SW_SCALE * (sVP[2 * al + 2] + sVP[2 * al + 3]);
                    q += (D[mi][ni][half * 2 + 0] - u0) * dw0
                       + (D[mi][ni][half * 2 + 1] - u1) * dw1;
                    li2 += dw0 * sDM[a] + dw1 * sDM[a + 1];
                }
                qacc[mi * 2 + half] += q;
                lacc[mi * 2 + half] += li2;
            }
        }
    }

#pragma unroll
    for (int i = 0; i < 4; i++) {
        qacc[i] += __shfl_xor_sync(~0u, qacc[i], 1);
        qacc[i] += __shfl_xor_sync(~0u, qacc[i], 2);
        lacc[i] += __shfl_xor_sync(~0u, lacc[i], 1);
        lacc[i] += __shfl_xor_sync(~0u, lacc[i], 2);
    }
    if ((lane & 3) == 0) {
#pragma unroll
        for (int i = 0; i < 4; i++) {
            const int row = wm * 32 + (i >> 1) * 16 + (i & 1) * 8 + (lane >> 2);
            sQ[row * 2 + wn] = qacc[i];
            sL[row * 2 + wn] = lacc[i];
        }
    }
    __syncthreads();
    if (t < 128) {
        const int c = c0 + t;
        if (c < C_DIM) {
            const float Lam = Lam_p[0];
            const float q = (sQ[t * 2] + sQ[t * 2 + 1]) * INV_PSCALE;
            const float li2 = sL[t * 2] + sL[t * 2 + 1];
            g_f4[ai][n][c] = 0.5f * Lam * q + Lam * li2;
        }
    }
}

// ---------------------------------------------------------------------------
// NLL + mean
// ---------------------------------------------------------------------------
__global__ void nll_kernel(const float* __restrict__ ys, const void* __restrict__ labels) {
    __shared__ float sm[128];
    const int n = blockIdx.x, t = threadIdx.x;
    const int sl = g_slot[n];
#define FSUM(c) (g_f4[0][sl][c] + g_f4[1][sl][c] + g_f4[2][sl][c] + g_f4[3][sl][c])
    const float v0 = ys[(size_t)n * C_DIM + t] + FSUM(t);
    const float v1 = ys[(size_t)n * C_DIM + t + 128] + FSUM(t + 128);
    const float v2 = (t + 256 < C_DIM)
                   ? ys[(size_t)n * C_DIM + t + 256] + FSUM(t + 256) : -1e30f;
    float mx = fmaxf(v0, fmaxf(v1, v2));
    sm[t] = mx; __syncthreads();
    for (int s = 64; s > 0; s >>= 1) { if (t < s) sm[t] = fmaxf(sm[t], sm[t + s]); __syncthreads(); }
    const float MX = sm[0]; __syncthreads();
    float e = expf(v0 - MX) + expf(v1 - MX);
    if (t + 256 < C_DIM) e += expf(v2 - MX);
    sm[t] = e; __syncthreads();
    for (int s = 64; s > 0; s >>= 1) { if (t < s) sm[t] += sm[t + s]; __syncthreads(); }
    if (t == 0) {
        const int l = get_label(labels, n, label_is64(labels));
        const float pick = ys[(size_t)n * C_DIM + l] + FSUM(l);
        g_nll[n] = logf(sm[0]) + MX - pick;
    }
#undef FSUM
}

__global__ void mean_kernel(float* __restrict__ out) {
    __shared__ float sm[128];
    const int t = threadIdx.x;
    sm[t] = g_nll[t]; __syncthreads();
    for (int s = 64; s > 0; s >>= 1) { if (t < s) sm[t] += sm[t + s]; __syncthreads(); }
    if (t == 0) out[0] = sm[0] * (1.0f / (float)N_DIM);
}

// ---------------------------------------------------------------------------
// Host launcher
// ---------------------------------------------------------------------------
extern "C" void kernel_launch(void* const* d_in, const int* in_sizes, int n_in,
                              void* d_out, int out_size) {
    const float* W      = (const float*)d_in[0];
    const float* ys     = (const float*)d_in[2];
    const void*  labels = d_in[3];
    const float* Lam    = (const float*)d_in[4];
    const float* ms     = (const float*)d_in[5];
    const float* mt     = (const float*)d_in[6];
    const float* cov    = (const float*)d_in[7];
    float* out = (float*)d_out;

    static int attr_set = 0;
    if (!attr_set) {
        cudaFuncSetAttribute(gemm_kernel, cudaFuncAttributeMaxDynamicSharedMemorySize,
                             SMEM_DYN);
        attr_set = 1;
    }

    prep_labels<<<1, N_DIM>>>(labels);
    prep_lbl<<<1, N_DIM>>>(labels);
    conv_w8<<<CPAD, 128>>>(W);
    conv_sig<<<dim3(256, 1, N_DIM), 256>>>(cov);
    gemm_kernel<<<dim3(3, 4, N_DIM), 256, SMEM_DYN>>>(W, Lam, ms, mt);
    nll_kernel<<<N_DIM, 128>>>(ys, labels);
    mean_kernel<<<1, 128>>>(out);
}